// round 16
// baseline (speedup 1.0000x reference)
#include <cuda_runtime.h>
#include <cuda_fp16.h>
#include <stdint.h>
#include <math.h>

#define NN   50000
#define EE   800000
#define ESL  (EE + NN)
#define INCH 128
#define HID  64
#define NH   4
#define HH   256
#define OUTN 16
#define OUTE 4
#define ROWS0 25088              // 196 blocks of 128
#define ROWS1 (NN - ROWS0)       // 24912

// ---------------- scratch (__device__ globals: allocation-free rule) ----------------
__device__ float  g_xp[(size_t)NN * HH];                 // layer-1 projected
__device__ float  g_xp2[(size_t)NN * HH];                // layer-2 projected
__device__ float  g_h1[(size_t)NN * HH];
__device__ float  g_als[NN * NH];
__device__ float  g_ald[NN * NH];
__device__ float  g_t[(size_t)NN * OUTE * HH];           // [N, 1024]
__device__ __half g_a2[(size_t)NN * (2 * HH)];           // fp16 split activations [ah|al]
__device__ __half g_b2a[(size_t)HH * (2 * INCH)];        // split W1 [bh|bh]
__device__ __half g_b2b[(size_t)HH * (2 * HH)];          // split W2
__device__ __half g_b2c[(size_t)(OUTE * HH) * (2 * HH)]; // split WbT
// CSR scratch
__device__ int g_cntd[NN], g_offd[NN + 1], g_curd[NN], g_srcd[ESL];
__device__ int g_cnts[NN], g_offs[NN + 1], g_curs[NN], g_dsts[EE], g_oids[EE];

// ---------------- helpers ----------------
__device__ __forceinline__ void ldsm_x4(unsigned &r0, unsigned &r1, unsigned &r2, unsigned &r3, unsigned addr) {
    asm volatile("ldmatrix.sync.aligned.m8n8.x4.shared.b16 {%0,%1,%2,%3}, [%4];"
                 : "=r"(r0), "=r"(r1), "=r"(r2), "=r"(r3) : "r"(addr));
}
__device__ __forceinline__ void mma_f16(float &c0, float &c1, float &c2, float &c3,
                                        unsigned a0, unsigned a1, unsigned a2, unsigned a3,
                                        unsigned b0, unsigned b1) {
    asm volatile("mma.sync.aligned.m16n8k16.row.col.f32.f16.f16.f32 "
                 "{%0,%1,%2,%3}, {%4,%5,%6,%7}, {%8,%9}, {%0,%1,%2,%3};"
                 : "+f"(c0), "+f"(c1), "+f"(c2), "+f"(c3)
                 : "r"(a0), "r"(a1), "r"(a2), "r"(a3), "r"(b0), "r"(b1));
}
__device__ __forceinline__ void cp16(unsigned dst, const void* src) {
    asm volatile("cp.async.cg.shared.global [%0], [%1], 16;" :: "r"(dst), "l"(src));
}
__device__ __forceinline__ unsigned pack_h2(float a, float b) {
    __half2 t = __floats2half2_rn(a, b);
    return *(unsigned*)&t;
}

// ---------------- CSR build ----------------
__global__ void k_hist(const int* __restrict__ ei) {
    int idx = blockIdx.x * blockDim.x + threadIdx.x;
    if (idx >= ESL) return;
    int d = (idx < EE) ? ei[EE + idx] : (idx - EE);
    atomicAdd(&g_cntd[d], 1);
    if (idx < EE) atomicAdd(&g_cnts[ei[idx]], 1);
}

__global__ void k_scan2() {
    int* cnt = blockIdx.x ? g_cnts : g_cntd;
    int* off = blockIdx.x ? g_offs : g_offd;
    int* cur = blockIdx.x ? g_curs : g_curd;
    __shared__ int part[1024];
    int tid = threadIdx.x;
    const int per = (NN + 1023) / 1024;
    int lo = tid * per, hi = min(lo + per, NN);
    int s = 0;
    for (int i = lo; i < hi; i++) s += cnt[i];
    part[tid] = s;
    __syncthreads();
    for (int d = 1; d < 1024; d <<= 1) {
        int v = (tid >= d) ? part[tid - d] : 0;
        __syncthreads();
        part[tid] += v;
        __syncthreads();
    }
    int run = tid ? part[tid - 1] : 0;
    for (int i = lo; i < hi; i++) { off[i] = run; cur[i] = run; run += cnt[i]; }
    if (tid == 1023) off[NN] = part[1023];
}

__global__ void k_scatter(const int* __restrict__ ei) {
    int idx = blockIdx.x * blockDim.x + threadIdx.x;
    if (idx >= ESL) return;
    int s = (idx < EE) ? ei[idx] : (idx - EE);
    int d = (idx < EE) ? ei[EE + idx] : (idx - EE);
    int pos = atomicAdd(&g_curd[d], 1);
    g_srcd[pos] = s;
    if (idx < EE) {
        int p2 = atomicAdd(&g_curs[s], 1);
        g_dsts[p2] = d;
        g_oids[p2] = idx;
    }
}

// ---------------- 2-term fp16 split (activations): out [R, 2K] = [ah | al] ----------------
__global__ void k_split2(const float* __restrict__ in, __half* __restrict__ out, int R, int K) {
    int idx = blockIdx.x * blockDim.x + threadIdx.x;
    if (idx >= R * K) return;
    int r = idx / K, k = idx - r * K;
    float v = in[idx];
    __half hi = __float2half(v);
    float lo = v - __half2float(hi);
    size_t base = (size_t)r * (2 * K);
    out[base + k] = hi;
    out[base + K + k] = __float2half(lo);
}

// fp32 weights W[R,K] -> split rows [bh | bh]
__global__ void k_wsplit2(const float* __restrict__ W, __half* __restrict__ out, int R, int K) {
    int idx = blockIdx.x * blockDim.x + threadIdx.x;
    if (idx >= R * K) return;
    int r = idx / K, k = idx - r * K;
    __half hi = __float2half(W[idx]);
    size_t base = (size_t)r * (2 * K);
    out[base + k] = hi;
    out[base + K + k] = hi;
}

// Wb[o,i,j] -> split-transposed row (o*HH+j): [bh(i) | bh(i)]
__global__ void k_wbt_split2(const float* __restrict__ Wb) {
    int idx = blockIdx.x * blockDim.x + threadIdx.x;
    if (idx >= OUTE * HH * HH) return;
    int o = idx / (HH * HH);
    int i = (idx / HH) % HH;
    int j = idx % HH;
    __half hi = __float2half(Wb[idx]);
    size_t base = ((size_t)o * HH + j) * (2 * HH);
    g_b2c[base + i] = hi;
    g_b2c[base + HH + i] = hi;
}

// ---------------- fp16 tensor-core GEMM: C[M,Nc] = A[M,K2] * B[Nc,K2]^T ----------------
// 128x128 block tile, BK=32, 4-stage cp.async pipeline, 8 warps (2x4) of 64x32. (R8/R15-proven)
#define SWZ(row, c) (((row) * 4 + ((c) ^ (((row) >> 1) & 3))) * 16)
__global__ void __launch_bounds__(256) gemm_f16_nt(const __half* __restrict__ A,
                                                   const __half* __restrict__ B,
                                                   float* __restrict__ C,
                                                   int M, int Nc, int K2) {
    __shared__ __half As[4][128 * 32];
    __shared__ __half Bs[4][128 * 32];
    const int tid = threadIdx.x;
    const int wid = tid >> 5, lane = tid & 31;
    const int bm = blockIdx.y * 128, bn = blockIdx.x * 128;
    const int wm = (wid >> 2) * 64, wn = (wid & 3) * 32;

    const unsigned as_base = (unsigned)__cvta_generic_to_shared(&As[0][0]);
    const unsigned bs_base = (unsigned)__cvta_generic_to_shared(&Bs[0][0]);

    float acc[4][4][4];
#pragma unroll
    for (int i = 0; i < 4; i++)
#pragma unroll
        for (int j = 0; j < 4; j++)
#pragma unroll
            for (int k = 0; k < 4; k++) acc[i][j][k] = 0.f;

    const int KT = K2 >> 5;
    const int lrow0 = tid >> 2, lrow1 = (tid >> 2) + 64, lc = tid & 3;

    auto load_stage = [&](int kt, int s) {
        const int k0 = kt * 32;
        const unsigned as_s = as_base + s * 8192;
        const unsigned bs_s = bs_base + s * 8192;
        {
            int gr = bm + lrow0;
            if (gr < M) cp16(as_s + SWZ(lrow0, lc), A + (size_t)gr * K2 + k0 + lc * 8);
            else { uint4 z = {0,0,0,0}; *(uint4*)&As[s][(size_t)(SWZ(lrow0, lc) >> 1)] = z; }
        }
        {
            int gr = bm + lrow1;
            if (gr < M) cp16(as_s + SWZ(lrow1, lc), A + (size_t)gr * K2 + k0 + lc * 8);
            else { uint4 z = {0,0,0,0}; *(uint4*)&As[s][(size_t)(SWZ(lrow1, lc) >> 1)] = z; }
        }
        {
            int gn = bn + lrow0;
            if (gn < Nc) cp16(bs_s + SWZ(lrow0, lc), B + (size_t)gn * K2 + k0 + lc * 8);
            else { uint4 z = {0,0,0,0}; *(uint4*)&Bs[s][(size_t)(SWZ(lrow0, lc) >> 1)] = z; }
        }
        {
            int gn = bn + lrow1;
            if (gn < Nc) cp16(bs_s + SWZ(lrow1, lc), B + (size_t)gn * K2 + k0 + lc * 8);
            else { uint4 z = {0,0,0,0}; *(uint4*)&Bs[s][(size_t)(SWZ(lrow1, lc) >> 1)] = z; }
        }
        asm volatile("cp.async.commit_group;");
    };

    load_stage(0, 0);
    load_stage(1, 1);
    load_stage(2, 2);
    for (int kt = 0; kt < KT; kt++) {
        const int s = kt & 3;
        asm volatile("cp.async.wait_group 2;");
        __syncthreads();
        if (kt + 3 < KT) load_stage(kt + 3, (kt + 3) & 3);

        const unsigned as_s = as_base + s * 8192;
        const unsigned bs_s = bs_base + s * 8192;
#pragma unroll
        for (int ks = 0; ks < 2; ks++) {
            unsigned a[4][4], b[2][4];
            const int kc = ks * 2 + (lane >> 4);
#pragma unroll
            for (int mf = 0; mf < 4; mf++) {
                int row = wm + mf * 16 + (lane & 15);
                ldsm_x4(a[mf][0], a[mf][1], a[mf][2], a[mf][3], as_s + SWZ(row, kc));
            }
#pragma unroll
            for (int nf2 = 0; nf2 < 2; nf2++) {
                int row = wn + nf2 * 16 + (lane & 15);
                ldsm_x4(b[nf2][0], b[nf2][1], b[nf2][2], b[nf2][3], bs_s + SWZ(row, kc));
            }
#pragma unroll
            for (int mf = 0; mf < 4; mf++)
#pragma unroll
                for (int nf = 0; nf < 4; nf++) {
                    int nf2 = nf >> 1, w = nf & 1;
                    mma_f16(acc[mf][nf][0], acc[mf][nf][1], acc[mf][nf][2], acc[mf][nf][3],
                            a[mf][0], a[mf][1], a[mf][2], a[mf][3],
                            b[nf2][w], b[nf2][w + 2]);
                }
        }
        __syncthreads();
    }

#pragma unroll
    for (int mf = 0; mf < 4; mf++)
#pragma unroll
        for (int nf = 0; nf < 4; nf++) {
            int r0 = bm + wm + mf * 16 + (lane >> 2);
            int c0 = bn + wn + nf * 8 + (lane & 3) * 2;
            if (c0 < Nc) {
                if (r0 < M) {
                    float2 v = {acc[mf][nf][0], acc[mf][nf][1]};
                    *(float2*)&C[(size_t)r0 * Nc + c0] = v;
                }
                if (r0 + 8 < M) {
                    float2 v = {acc[mf][nf][2], acc[mf][nf][3]};
                    *(float2*)&C[(size_t)(r0 + 8) * Nc + c0] = v;
                }
            }
        }
}
#undef SWZ

// ---------------- attention logits: warp per node, coalesced ----------------
__global__ void k_al(const float* __restrict__ xp,
                     const float* __restrict__ a_s, const float* __restrict__ a_d) {
    int n = (blockIdx.x * blockDim.x + threadIdx.x) >> 5;
    int lane = threadIdx.x & 31;
    if (n >= NN) return;
    int hb = lane >> 3, w = lane & 7;
    const float4* xr = (const float4*)(xp + (size_t)n * HH);
    float4 v0 = xr[hb * 16 + w * 2];
    float4 v1 = xr[hb * 16 + w * 2 + 1];
    const float4* as4 = (const float4*)a_s;
    const float4* ad4 = (const float4*)a_d;
    float4 s0 = __ldg(&as4[hb * 16 + w * 2]), s1 = __ldg(&as4[hb * 16 + w * 2 + 1]);
    float4 d0 = __ldg(&ad4[hb * 16 + w * 2]), d1 = __ldg(&ad4[hb * 16 + w * 2 + 1]);
    float ps = v0.x * s0.x + v0.y * s0.y + v0.z * s0.z + v0.w * s0.w
             + v1.x * s1.x + v1.y * s1.y + v1.z * s1.z + v1.w * s1.w;
    float pd = v0.x * d0.x + v0.y * d0.y + v0.z * d0.z + v0.w * d0.w
             + v1.x * d1.x + v1.y * d1.y + v1.z * d1.z + v1.w * d1.w;
#pragma unroll
    for (int off = 1; off < 8; off <<= 1) {
        ps += __shfl_xor_sync(0xffffffffu, ps, off);
        pd += __shfl_xor_sync(0xffffffffu, pd, off);
    }
    if (w == 0) {
        g_als[n * NH + hb] = ps;
        g_ald[n * NH + hb] = pd;
    }
}

// ---------------- fused GAT aggregation: warp per dst node, node range [n0, nend) ----------------
__global__ void k_gat(const float* __restrict__ xp, const float* __restrict__ bias,
                      float* __restrict__ outh, __half* __restrict__ a2out,
                      int n0, int nend) {
    int n = n0 + ((blockIdx.x * blockDim.x + threadIdx.x) >> 5);
    int lane = threadIdx.x & 31;
    if (n >= nend) return;
    int start = g_offd[n], end = g_offd[n + 1];

    // phase A: lane handles edges start+q (stride 8) for head h; online softmax
    int h = lane & 3, q = lane >> 2;
    float ald_h = g_ald[n * NH + h];
    float m = -1e30f, den = 0.f;
    for (int j = start + q; j < end; j += 8) {
        int s = g_srcd[j];
        float a = g_als[s * NH + h] + ald_h;
        a = (a > 0.f) ? a : 0.2f * a;
        if (a > m) { den = den * expf(m - a) + 1.f; m = a; }
        else den += expf(a - m);
    }
#pragma unroll
    for (int off = 4; off < 32; off <<= 1) {
        float mo = __shfl_xor_sync(0xffffffffu, m, off);
        float dn = __shfl_xor_sync(0xffffffffu, den, off);
        float mn = fmaxf(m, mo);
        den = den * expf(m - mn) + dn * expf(mo - mn);
        m = mn;
    }
    __syncwarp();

    // phase B: lane covers channels [lane*8, lane*8+8), head hb = lane>>3
    int hb = lane >> 3;
    float mB = __shfl_sync(0xffffffffu, m, hb);
    float dB = __shfl_sync(0xffffffffu, den, hb);
    float ald_hb = g_ald[n * NH + hb];
    float inv = 1.f / (dB + 1e-16f);
    float4 a0 = {0, 0, 0, 0}, a1 = {0, 0, 0, 0};
    for (int j = start; j < end; j++) {
        int s = g_srcd[j];
        float al = g_als[s * NH + hb] + ald_hb;
        al = (al > 0.f) ? al : 0.2f * al;
        float coef = expf(al - mB) * inv;
        const float4* xr = (const float4*)(xp + (size_t)s * HH);
        float4 v0 = xr[lane * 2], v1 = xr[lane * 2 + 1];
        a0.x += v0.x * coef; a0.y += v0.y * coef; a0.z += v0.z * coef; a0.w += v0.w * coef;
        a1.x += v1.x * coef; a1.y += v1.y * coef; a1.z += v1.z * coef; a1.w += v1.w * coef;
    }

    // epilogue: bias + ELU
    const float4* b4 = (const float4*)bias;
    float4 bb0 = __ldg(&b4[lane * 2]), bb1 = __ldg(&b4[lane * 2 + 1]);
    float v[8];
    v[0] = a0.x + bb0.x; v[1] = a0.y + bb0.y; v[2] = a0.z + bb0.z; v[3] = a0.w + bb0.w;
    v[4] = a1.x + bb1.x; v[5] = a1.y + bb1.y; v[6] = a1.z + bb1.z; v[7] = a1.w + bb1.w;
#pragma unroll
    for (int i = 0; i < 8; i++) v[i] = (v[i] > 0.f) ? v[i] : expm1f(v[i]);

    float4* orow = (float4*)(outh + (size_t)n * HH);
    float4 o0 = {v[0], v[1], v[2], v[3]}, o1 = {v[4], v[5], v[6], v[7]};
    orow[lane * 2] = o0;
    orow[lane * 2 + 1] = o1;

    // fp16 2-term split: [ah(256) | al(256)]
    unsigned hi_p[4], lo_p[4];
#pragma unroll
    for (int i = 0; i < 4; i++) {
        __half h0 = __float2half(v[2 * i]);
        __half h1 = __float2half(v[2 * i + 1]);
        float l0 = v[2 * i] - __half2float(h0);
        float l1 = v[2 * i + 1] - __half2float(h1);
        __half2 hp; hp.x = h0; hp.y = h1;
        hi_p[i] = *(unsigned*)&hp;
        lo_p[i] = pack_h2(l0, l1);
    }
    __half* arow = a2out + (size_t)n * (2 * HH);
    uint4 hv = {hi_p[0], hi_p[1], hi_p[2], hi_p[3]};
    uint4 lv = {lo_p[0], lo_p[1], lo_p[2], lo_p[3]};
    ((uint4*)(arow))[lane] = hv;
    ((uint4*)(arow + HH))[lane] = lv;
}

// ---------------- node predictor: warp per node, Wn in smem ----------------
__global__ void __launch_bounds__(256) k_nodepred(const float* __restrict__ h,
                                                  const float* __restrict__ Wn,
                                                  const float* __restrict__ bn,
                                                  float* __restrict__ out) {
    __shared__ float sW[OUTN * HH];
    int tid = threadIdx.x;
    for (int i = tid; i < OUTN * HH; i += 256) sW[i] = Wn[i];
    __syncthreads();
    int n = (blockIdx.x * 256 + tid) >> 5;
    int lane = tid & 31;
    if (n >= NN) return;
    const float4* hr = (const float4*)(h + (size_t)n * HH);
    float4 v0 = hr[lane * 2], v1 = hr[lane * 2 + 1];
    float p[OUTN];
#pragma unroll
    for (int o = 0; o < OUTN; o++) {
        const float4* wr = (const float4*)(sW + o * HH);
        float4 w0 = wr[lane * 2], w1 = wr[lane * 2 + 1];
        p[o] = v0.x * w0.x + v0.y * w0.y + v0.z * w0.z + v0.w * w0.w
             + v1.x * w1.x + v1.y * w1.y + v1.z * w1.z + v1.w * w1.w;
    }
#pragma unroll
    for (int off = 16; off > 0; off >>= 1)
#pragma unroll
        for (int o = 0; o < OUTN; o++)
            p[o] += __shfl_xor_sync(0xffffffffu, p[o], off);
    if (lane < OUTN) out[(size_t)n * OUTN + lane] = p[lane] + __ldg(&bn[lane]);
}

// ---------------- edge bilinear: warp per src node in [n0, nend), t in registers ----------------
__global__ void k_bil(const float* __restrict__ h2, const float* __restrict__ bb,
                      float* __restrict__ out_edge, int n0, int nend) {
    int n = n0 + ((blockIdx.x * blockDim.x + threadIdx.x) >> 5);
    int lane = threadIdx.x & 31;
    if (n >= nend) return;
    int start = g_offs[n], end = g_offs[n + 1];
    if (start == end) return;

    const float4* tp = (const float4*)(g_t + (size_t)n * (OUTE * HH));
    float4 t0[OUTE], t1[OUTE];
#pragma unroll
    for (int o = 0; o < OUTE; o++) {
        t0[o] = tp[o * 64 + lane * 2];
        t1[o] = tp[o * 64 + lane * 2 + 1];
    }
    float myb = (lane < OUTE) ? __ldg(&bb[lane]) : 0.f;

    for (int j = start; j < end; j++) {
        int d = g_dsts[j];
        int orig = g_oids[j];
        const float4* hr = (const float4*)(h2 + (size_t)d * HH);
        float4 v0 = hr[lane * 2], v1 = hr[lane * 2 + 1];
        float p[OUTE];
#pragma unroll
        for (int o = 0; o < OUTE; o++)
            p[o] = t0[o].x * v0.x + t0[o].y * v0.y + t0[o].z * v0.z + t0[o].w * v0.w
                 + t1[o].x * v1.x + t1[o].y * v1.y + t1[o].z * v1.z + t1[o].w * v1.w;
#pragma unroll
        for (int off = 16; off > 0; off >>= 1)
#pragma unroll
            for (int o = 0; o < OUTE; o++)
                p[o] += __shfl_xor_sync(0xffffffffu, p[o], off);
        if (lane < OUTE) {
            float r = (lane == 0) ? p[0] : (lane == 1) ? p[1] : (lane == 2) ? p[2] : p[3];
            out_edge[(size_t)orig * OUTE + lane] = r + myb;
        }
    }
}

// ---------------- host ----------------
extern "C" void kernel_launch(void* const* d_in, const int* in_sizes, int n_in,
                              void* d_out, int out_size) {
    const float* x   = (const float*)d_in[0];
    const int*   ei  = (const int*)d_in[1];
    const float* W1  = (const float*)d_in[2];
    const float* as1 = (const float*)d_in[3];
    const float* ad1 = (const float*)d_in[4];
    const float* b1  = (const float*)d_in[5];
    const float* W2  = (const float*)d_in[6];
    const float* as2 = (const float*)d_in[7];
    const float* ad2 = (const float*)d_in[8];
    const float* b2  = (const float*)d_in[9];
    const float* Wn  = (const float*)d_in[10];
    const float* bn  = (const float*)d_in[11];
    const float* Wb  = (const float*)d_in[12];
    const float* bb  = (const float*)d_in[13];

    float* out_node = (float*)d_out;
    float* out_edge = out_node + (size_t)NN * OUTN;
    float* out_h    = out_edge + (size_t)EE * OUTE;

    float *p_xp, *p_xp2, *p_h1, *p_t;
    __half *p_a2, *p_b2a, *p_b2b, *p_b2c;
    int *p_cntd, *p_cnts;
    cudaGetSymbolAddress((void**)&p_xp, g_xp);
    cudaGetSymbolAddress((void**)&p_xp2, g_xp2);
    cudaGetSymbolAddress((void**)&p_h1, g_h1);
    cudaGetSymbolAddress((void**)&p_t, g_t);
    cudaGetSymbolAddress((void**)&p_a2, g_a2);
    cudaGetSymbolAddress((void**)&p_b2a, g_b2a);
    cudaGetSymbolAddress((void**)&p_b2b, g_b2b);
    cudaGetSymbolAddress((void**)&p_b2c, g_b2c);
    cudaGetSymbolAddress((void**)&p_cntd, g_cntd);
    cudaGetSymbolAddress((void**)&p_cnts, g_cnts);

    // one-time host resources
    static cudaStream_t s2 = nullptr;
    static cudaEvent_t e0, e2, e_g1h0, e_G2h0, e_g2h0, e_g2h1, e_s2;
    if (!s2) {
        cudaStreamCreateWithFlags(&s2, cudaStreamNonBlocking);
        cudaEventCreateWithFlags(&e0, cudaEventDisableTiming);
        cudaEventCreateWithFlags(&e2, cudaEventDisableTiming);
        cudaEventCreateWithFlags(&e_g1h0, cudaEventDisableTiming);
        cudaEventCreateWithFlags(&e_G2h0, cudaEventDisableTiming);
        cudaEventCreateWithFlags(&e_g2h0, cudaEventDisableTiming);
        cudaEventCreateWithFlags(&e_g2h1, cudaEventDisableTiming);
        cudaEventCreateWithFlags(&e_s2, cudaEventDisableTiming);
    }

    dim3 blk(256);
    int g_nodeW = (NN * 32 + 255) / 256;
    int g_h0W   = (ROWS0 * 32 + 255) / 256;
    int g_h1W   = (ROWS1 * 32 + 255) / 256;
    int g_esl   = (ESL + 255) / 256;

    // ---- fork: CSR build + weight splits on s2 ----
    cudaEventRecord(e0, 0);
    cudaStreamWaitEvent(s2, e0, 0);
    cudaMemsetAsync(p_cntd, 0, NN * sizeof(int), s2);
    cudaMemsetAsync(p_cnts, 0, NN * sizeof(int), s2);
    k_hist<<<g_esl, blk, 0, s2>>>(ei);
    k_scan2<<<2, 1024, 0, s2>>>();
    k_scatter<<<g_esl, blk, 0, s2>>>(ei);
    k_wsplit2<<<(HH * HH + 255) / 256, blk, 0, s2>>>(W2, p_b2b, HH, HH);
    k_wbt_split2<<<(OUTE * HH * HH + 255) / 256, blk, 0, s2>>>(Wb);
    cudaEventRecord(e2, s2);

    // ---- main: layer-1 GEMM path ----
    k_split2<<<(NN * INCH + 255) / 256, blk>>>(x, p_a2, NN, INCH);
    k_wsplit2<<<(HH * INCH + 255) / 256, blk>>>(W1, p_b2a, HH, INCH);
    {
        dim3 grid(2, (NN + 127) / 128);
        gemm_f16_nt<<<grid, blk>>>(p_a2, p_b2a, p_xp, NN, HH, 2 * INCH);
    }
    k_al<<<g_nodeW, blk>>>(p_xp, as1, ad1);
    cudaStreamWaitEvent(0, e2, 0);                 // join: CSR ready
    // ---- k_gat1 halves; GEMM2(h0) overlaps k_gat1(h1) ----
    k_gat<<<g_h0W, blk>>>(p_xp, b1, p_h1, p_a2, 0, ROWS0);
    cudaEventRecord(e_g1h0, 0);
    k_gat<<<g_h1W, blk>>>(p_xp, b1, p_h1, p_a2, ROWS0, NN);

    cudaStreamWaitEvent(s2, e_g1h0, 0);
    {
        dim3 grid(2, ROWS0 / 128);
        gemm_f16_nt<<<grid, blk, 0, s2>>>(p_a2, p_b2b, p_xp2, ROWS0, HH, 2 * HH);
    }
    cudaEventRecord(e_G2h0, s2);

    {
        dim3 grid(2, (ROWS1 + 127) / 128);
        gemm_f16_nt<<<grid, blk>>>(p_a2 + (size_t)ROWS0 * (2 * HH), p_b2b,
                                   p_xp2 + (size_t)ROWS0 * HH, ROWS1, HH, 2 * HH);
    }
    cudaStreamWaitEvent(0, e_G2h0, 0);             // need full xp2
    k_al<<<g_nodeW, blk>>>(p_xp2, as2, ad2);
    // ---- k_gat2 halves; t-GEMM(h0) overlaps k_gat2(h1) ----
    k_gat<<<g_h0W, blk>>>(p_xp2, b2, out_h, p_a2, 0, ROWS0);
    cudaEventRecord(e_g2h0, 0);
    k_gat<<<g_h1W, blk>>>(p_xp2, b2, out_h, p_a2, ROWS0, NN);
    cudaEventRecord(e_g2h1, 0);

    cudaStreamWaitEvent(s2, e_g2h0, 0);
    {
        dim3 grid((OUTE * HH) / 128, ROWS0 / 128);
        gemm_f16_nt<<<grid, blk, 0, s2>>>(p_a2, p_b2c, p_t, ROWS0, OUTE * HH, 2 * HH);
    }
    cudaStreamWaitEvent(s2, e_g2h1, 0);            // out_h full for nodepred/k_bil
    k_nodepred<<<(NN * 32 + 255) / 256, blk, 0, s2>>>(out_h, Wn, bn, out_node);
    k_bil<<<g_h0W, blk, 0, s2>>>(out_h, bb, out_edge, 0, ROWS0);
    cudaEventRecord(e_s2, s2);

    // main: t-GEMM(h1) runs concurrent with s2's nodepred + k_bil(h0)
    {
        dim3 grid((OUTE * HH) / 128, (ROWS1 + 127) / 128);
        gemm_f16_nt<<<grid, blk>>>(p_a2 + (size_t)ROWS0 * (2 * HH), p_b2c,
                                   p_t + (size_t)ROWS0 * (OUTE * HH), ROWS1, OUTE * HH, 2 * HH);
    }
    k_bil<<<g_h1W, blk>>>(out_h, bb, out_edge, ROWS0, NN);
    cudaStreamWaitEvent(0, e_s2, 0);               // join before return
}

// round 17
// speedup vs baseline: 1.0230x; 1.0230x over previous
#include <cuda_runtime.h>
#include <cuda_fp16.h>
#include <stdint.h>
#include <math.h>

#define NN   50000
#define EE   800000
#define ESL  (EE + NN)
#define INCH 128
#define HID  64
#define NH   4
#define HH   256
#define OUTN 16
#define OUTE 4

// ---------------- scratch (__device__ globals: allocation-free rule) ----------------
__device__ float  g_xp[(size_t)NN * HH];
__device__ float  g_h1[(size_t)NN * HH];
__device__ float  g_als[NN * NH];
__device__ float  g_ald[NN * NH];
__device__ __half g_t[(size_t)NN * OUTE * HH];           // [N, 1024] fp16 (halved traffic)
__device__ __half g_a2[(size_t)NN * (2 * HH)];           // 2-term fp16 split activations [ah|al]
__device__ __half g_b2a[(size_t)HH * (2 * INCH)];        // split W1 [bh|bh]
__device__ __half g_b2b[(size_t)HH * (2 * HH)];          // split W2
__device__ __half g_b2c[(size_t)(OUTE * HH) * (2 * HH)]; // split WbT
// CSR scratch
__device__ int g_cntd[NN], g_offd[NN + 1], g_curd[NN], g_srcd[ESL];
__device__ int g_cnts[NN], g_offs[NN + 1], g_curs[NN], g_dsts[EE], g_oids[EE];

// ---------------- helpers ----------------
__device__ __forceinline__ void ldsm_x4(unsigned &r0, unsigned &r1, unsigned &r2, unsigned &r3, unsigned addr) {
    asm volatile("ldmatrix.sync.aligned.m8n8.x4.shared.b16 {%0,%1,%2,%3}, [%4];"
                 : "=r"(r0), "=r"(r1), "=r"(r2), "=r"(r3) : "r"(addr));
}
__device__ __forceinline__ void mma_f16(float &c0, float &c1, float &c2, float &c3,
                                        unsigned a0, unsigned a1, unsigned a2, unsigned a3,
                                        unsigned b0, unsigned b1) {
    asm volatile("mma.sync.aligned.m16n8k16.row.col.f32.f16.f16.f32 "
                 "{%0,%1,%2,%3}, {%4,%5,%6,%7}, {%8,%9}, {%0,%1,%2,%3};"
                 : "+f"(c0), "+f"(c1), "+f"(c2), "+f"(c3)
                 : "r"(a0), "r"(a1), "r"(a2), "r"(a3), "r"(b0), "r"(b1));
}
__device__ __forceinline__ void cp16(unsigned dst, const void* src) {
    asm volatile("cp.async.cg.shared.global [%0], [%1], 16;" :: "r"(dst), "l"(src));
}
__device__ __forceinline__ unsigned pack_h2(float a, float b) {
    __half2 t = __floats2half2_rn(a, b);
    return *(unsigned*)&t;
}

// ---------------- CSR build ----------------
__global__ void k_hist(const int* __restrict__ ei) {
    int idx = blockIdx.x * blockDim.x + threadIdx.x;
    if (idx >= ESL) return;
    int d = (idx < EE) ? ei[EE + idx] : (idx - EE);
    atomicAdd(&g_cntd[d], 1);
    if (idx < EE) atomicAdd(&g_cnts[ei[idx]], 1);
}

__global__ void k_scan2() {
    int* cnt = blockIdx.x ? g_cnts : g_cntd;
    int* off = blockIdx.x ? g_offs : g_offd;
    int* cur = blockIdx.x ? g_curs : g_curd;
    __shared__ int part[1024];
    int tid = threadIdx.x;
    const int per = (NN + 1023) / 1024;
    int lo = tid * per, hi = min(lo + per, NN);
    int s = 0;
    for (int i = lo; i < hi; i++) s += cnt[i];
    part[tid] = s;
    __syncthreads();
    for (int d = 1; d < 1024; d <<= 1) {
        int v = (tid >= d) ? part[tid - d] : 0;
        __syncthreads();
        part[tid] += v;
        __syncthreads();
    }
    int run = tid ? part[tid - 1] : 0;
    for (int i = lo; i < hi; i++) { off[i] = run; cur[i] = run; run += cnt[i]; }
    if (tid == 1023) off[NN] = part[1023];
}

__global__ void k_scatter(const int* __restrict__ ei) {
    int idx = blockIdx.x * blockDim.x + threadIdx.x;
    if (idx >= ESL) return;
    int s = (idx < EE) ? ei[idx] : (idx - EE);
    int d = (idx < EE) ? ei[EE + idx] : (idx - EE);
    int pos = atomicAdd(&g_curd[d], 1);
    g_srcd[pos] = s;
    if (idx < EE) {
        int p2 = atomicAdd(&g_curs[s], 1);
        g_dsts[p2] = d;
        g_oids[p2] = idx;
    }
}

// ---------------- 2-term fp16 split (activations): out [R, 2K] = [ah | al] ----------------
__global__ void k_split2(const float* __restrict__ in, __half* __restrict__ out, int R, int K) {
    int idx = blockIdx.x * blockDim.x + threadIdx.x;
    if (idx >= R * K) return;
    int r = idx / K, k = idx - r * K;
    float v = in[idx];
    __half hi = __float2half(v);
    float lo = v - __half2float(hi);
    size_t base = (size_t)r * (2 * K);
    out[base + k] = hi;
    out[base + K + k] = __float2half(lo);
}

// fp32 weights W[R,K] -> split rows [bh | bh]
__global__ void k_wsplit2(const float* __restrict__ W, __half* __restrict__ out, int R, int K) {
    int idx = blockIdx.x * blockDim.x + threadIdx.x;
    if (idx >= R * K) return;
    int r = idx / K, k = idx - r * K;
    __half hi = __float2half(W[idx]);
    size_t base = (size_t)r * (2 * K);
    out[base + k] = hi;
    out[base + K + k] = hi;
}

// Wb[o,i,j] -> split-transposed row (o*HH+j): [bh(i) | bh(i)]
__global__ void k_wbt_split2(const float* __restrict__ Wb) {
    int idx = blockIdx.x * blockDim.x + threadIdx.x;
    if (idx >= OUTE * HH * HH) return;
    int o = idx / (HH * HH);
    int i = (idx / HH) % HH;
    int j = idx % HH;
    __half hi = __float2half(Wb[idx]);
    size_t base = ((size_t)o * HH + j) * (2 * HH);
    g_b2c[base + i] = hi;
    g_b2c[base + HH + i] = hi;
}

// ---------------- fp16 tensor-core GEMM: C[M,Nc] = A[M,K2] * B[Nc,K2]^T ----------------
// 128x128 block tile, BK=32, 4-stage cp.async pipeline, 8 warps (2x4) of 64x32. (R15-proven)
// If Ch != nullptr, output is fp16 (half2 stores); else fp32 via C.
#define SWZ(row, c) (((row) * 4 + ((c) ^ (((row) >> 1) & 3))) * 16)
__global__ void __launch_bounds__(256) gemm_f16_nt(const __half* __restrict__ A,
                                                   const __half* __restrict__ B,
                                                   float* __restrict__ C,
                                                   __half* __restrict__ Ch,
                                                   int M, int Nc, int K2) {
    __shared__ __half As[4][128 * 32];
    __shared__ __half Bs[4][128 * 32];
    const int tid = threadIdx.x;
    const int wid = tid >> 5, lane = tid & 31;
    const int bm = blockIdx.y * 128, bn = blockIdx.x * 128;
    const int wm = (wid >> 2) * 64, wn = (wid & 3) * 32;

    const unsigned as_base = (unsigned)__cvta_generic_to_shared(&As[0][0]);
    const unsigned bs_base = (unsigned)__cvta_generic_to_shared(&Bs[0][0]);

    float acc[4][4][4];
#pragma unroll
    for (int i = 0; i < 4; i++)
#pragma unroll
        for (int j = 0; j < 4; j++)
#pragma unroll
            for (int k = 0; k < 4; k++) acc[i][j][k] = 0.f;

    const int KT = K2 >> 5;
    const int lrow0 = tid >> 2, lrow1 = (tid >> 2) + 64, lc = tid & 3;

    auto load_stage = [&](int kt, int s) {
        const int k0 = kt * 32;
        const unsigned as_s = as_base + s * 8192;
        const unsigned bs_s = bs_base + s * 8192;
        {
            int gr = bm + lrow0;
            if (gr < M) cp16(as_s + SWZ(lrow0, lc), A + (size_t)gr * K2 + k0 + lc * 8);
            else { uint4 z = {0,0,0,0}; *(uint4*)&As[s][(size_t)(SWZ(lrow0, lc) >> 1)] = z; }
        }
        {
            int gr = bm + lrow1;
            if (gr < M) cp16(as_s + SWZ(lrow1, lc), A + (size_t)gr * K2 + k0 + lc * 8);
            else { uint4 z = {0,0,0,0}; *(uint4*)&As[s][(size_t)(SWZ(lrow1, lc) >> 1)] = z; }
        }
        {
            int gn = bn + lrow0;
            if (gn < Nc) cp16(bs_s + SWZ(lrow0, lc), B + (size_t)gn * K2 + k0 + lc * 8);
            else { uint4 z = {0,0,0,0}; *(uint4*)&Bs[s][(size_t)(SWZ(lrow0, lc) >> 1)] = z; }
        }
        {
            int gn = bn + lrow1;
            if (gn < Nc) cp16(bs_s + SWZ(lrow1, lc), B + (size_t)gn * K2 + k0 + lc * 8);
            else { uint4 z = {0,0,0,0}; *(uint4*)&Bs[s][(size_t)(SWZ(lrow1, lc) >> 1)] = z; }
        }
        asm volatile("cp.async.commit_group;");
    };

    load_stage(0, 0);
    load_stage(1, 1);
    load_stage(2, 2);
    for (int kt = 0; kt < KT; kt++) {
        const int s = kt & 3;
        asm volatile("cp.async.wait_group 2;");
        __syncthreads();
        if (kt + 3 < KT) load_stage(kt + 3, (kt + 3) & 3);

        const unsigned as_s = as_base + s * 8192;
        const unsigned bs_s = bs_base + s * 8192;
#pragma unroll
        for (int ks = 0; ks < 2; ks++) {
            unsigned a[4][4], b[2][4];
            const int kc = ks * 2 + (lane >> 4);
#pragma unroll
            for (int mf = 0; mf < 4; mf++) {
                int row = wm + mf * 16 + (lane & 15);
                ldsm_x4(a[mf][0], a[mf][1], a[mf][2], a[mf][3], as_s + SWZ(row, kc));
            }
#pragma unroll
            for (int nf2 = 0; nf2 < 2; nf2++) {
                int row = wn + nf2 * 16 + (lane & 15);
                ldsm_x4(b[nf2][0], b[nf2][1], b[nf2][2], b[nf2][3], bs_s + SWZ(row, kc));
            }
#pragma unroll
            for (int mf = 0; mf < 4; mf++)
#pragma unroll
                for (int nf = 0; nf < 4; nf++) {
                    int nf2 = nf >> 1, w = nf & 1;
                    mma_f16(acc[mf][nf][0], acc[mf][nf][1], acc[mf][nf][2], acc[mf][nf][3],
                            a[mf][0], a[mf][1], a[mf][2], a[mf][3],
                            b[nf2][w], b[nf2][w + 2]);
                }
        }
        __syncthreads();
    }

#pragma unroll
    for (int mf = 0; mf < 4; mf++)
#pragma unroll
        for (int nf = 0; nf < 4; nf++) {
            int r0 = bm + wm + mf * 16 + (lane >> 2);
            int c0 = bn + wn + nf * 8 + (lane & 3) * 2;
            if (c0 < Nc) {
                if (Ch) {
                    if (r0 < M)
                        *(__half2*)&Ch[(size_t)r0 * Nc + c0] =
                            __floats2half2_rn(acc[mf][nf][0], acc[mf][nf][1]);
                    if (r0 + 8 < M)
                        *(__half2*)&Ch[(size_t)(r0 + 8) * Nc + c0] =
                            __floats2half2_rn(acc[mf][nf][2], acc[mf][nf][3]);
                } else {
                    if (r0 < M) {
                        float2 v = {acc[mf][nf][0], acc[mf][nf][1]};
                        *(float2*)&C[(size_t)r0 * Nc + c0] = v;
                    }
                    if (r0 + 8 < M) {
                        float2 v = {acc[mf][nf][2], acc[mf][nf][3]};
                        *(float2*)&C[(size_t)(r0 + 8) * Nc + c0] = v;
                    }
                }
            }
        }
}
#undef SWZ

// ---------------- attention logits: warp per node, coalesced ----------------
__global__ void k_al(const float* __restrict__ a_s, const float* __restrict__ a_d) {
    int n = (blockIdx.x * blockDim.x + threadIdx.x) >> 5;
    int lane = threadIdx.x & 31;
    if (n >= NN) return;
    int hb = lane >> 3, w = lane & 7;
    const float4* xr = (const float4*)(g_xp + (size_t)n * HH);
    float4 v0 = xr[hb * 16 + w * 2];
    float4 v1 = xr[hb * 16 + w * 2 + 1];
    const float4* as4 = (const float4*)a_s;
    const float4* ad4 = (const float4*)a_d;
    float4 s0 = __ldg(&as4[hb * 16 + w * 2]), s1 = __ldg(&as4[hb * 16 + w * 2 + 1]);
    float4 d0 = __ldg(&ad4[hb * 16 + w * 2]), d1 = __ldg(&ad4[hb * 16 + w * 2 + 1]);
    float ps = v0.x * s0.x + v0.y * s0.y + v0.z * s0.z + v0.w * s0.w
             + v1.x * s1.x + v1.y * s1.y + v1.z * s1.z + v1.w * s1.w;
    float pd = v0.x * d0.x + v0.y * d0.y + v0.z * d0.z + v0.w * d0.w
             + v1.x * d1.x + v1.y * d1.y + v1.z * d1.z + v1.w * d1.w;
#pragma unroll
    for (int off = 1; off < 8; off <<= 1) {
        ps += __shfl_xor_sync(0xffffffffu, ps, off);
        pd += __shfl_xor_sync(0xffffffffu, pd, off);
    }
    if (w == 0) {
        g_als[n * NH + hb] = ps;
        g_ald[n * NH + hb] = pd;
    }
}

// ---------------- fused GAT aggregation: warp per dst node ----------------
__global__ void k_gat(const float* __restrict__ bias, float* __restrict__ outh,
                      __half* __restrict__ a2out) {
    int n = (blockIdx.x * blockDim.x + threadIdx.x) >> 5;
    int lane = threadIdx.x & 31;
    if (n >= NN) return;
    int start = g_offd[n], end = g_offd[n + 1];

    // phase A: lane handles edges start+q (stride 8) for head h; online softmax
    int h = lane & 3, q = lane >> 2;
    float ald_h = g_ald[n * NH + h];
    float m = -1e30f, den = 0.f;
    for (int j = start + q; j < end; j += 8) {
        int s = g_srcd[j];
        float a = g_als[s * NH + h] + ald_h;
        a = (a > 0.f) ? a : 0.2f * a;
        if (a > m) { den = den * expf(m - a) + 1.f; m = a; }
        else den += expf(a - m);
    }
#pragma unroll
    for (int off = 4; off < 32; off <<= 1) {
        float mo = __shfl_xor_sync(0xffffffffu, m, off);
        float dn = __shfl_xor_sync(0xffffffffu, den, off);
        float mn = fmaxf(m, mo);
        den = den * expf(m - mn) + dn * expf(mo - mn);
        m = mn;
    }
    __syncwarp();

    // phase B: lane covers channels [lane*8, lane*8+8), head hb = lane>>3
    int hb = lane >> 3;
    float mB = __shfl_sync(0xffffffffu, m, hb);
    float dB = __shfl_sync(0xffffffffu, den, hb);
    float ald_hb = g_ald[n * NH + hb];
    float inv = 1.f / (dB + 1e-16f);
    float4 a0 = {0, 0, 0, 0}, a1 = {0, 0, 0, 0};
    for (int j = start; j < end; j++) {
        int s = g_srcd[j];
        float al = g_als[s * NH + hb] + ald_hb;
        al = (al > 0.f) ? al : 0.2f * al;
        float coef = expf(al - mB) * inv;
        const float4* xr = (const float4*)(g_xp + (size_t)s * HH);
        float4 v0 = xr[lane * 2], v1 = xr[lane * 2 + 1];
        a0.x += v0.x * coef; a0.y += v0.y * coef; a0.z += v0.z * coef; a0.w += v0.w * coef;
        a1.x += v1.x * coef; a1.y += v1.y * coef; a1.z += v1.z * coef; a1.w += v1.w * coef;
    }

    // epilogue: bias + ELU
    const float4* b4 = (const float4*)bias;
    float4 bb0 = __ldg(&b4[lane * 2]), bb1 = __ldg(&b4[lane * 2 + 1]);
    float v[8];
    v[0] = a0.x + bb0.x; v[1] = a0.y + bb0.y; v[2] = a0.z + bb0.z; v[3] = a0.w + bb0.w;
    v[4] = a1.x + bb1.x; v[5] = a1.y + bb1.y; v[6] = a1.z + bb1.z; v[7] = a1.w + bb1.w;
#pragma unroll
    for (int i = 0; i < 8; i++) v[i] = (v[i] > 0.f) ? v[i] : expm1f(v[i]);

    float4* orow = (float4*)(outh + (size_t)n * HH);
    float4 o0 = {v[0], v[1], v[2], v[3]}, o1 = {v[4], v[5], v[6], v[7]};
    orow[lane * 2] = o0;
    orow[lane * 2 + 1] = o1;

    // fp16 2-term split: [ah(256) | al(256)]
    unsigned hi_p[4], lo_p[4];
#pragma unroll
    for (int i = 0; i < 4; i++) {
        __half h0 = __float2half(v[2 * i]);
        __half h1 = __float2half(v[2 * i + 1]);
        float l0 = v[2 * i] - __half2float(h0);
        float l1 = v[2 * i + 1] - __half2float(h1);
        __half2 hp; hp.x = h0; hp.y = h1;
        hi_p[i] = *(unsigned*)&hp;
        lo_p[i] = pack_h2(l0, l1);
    }
    __half* arow = a2out + (size_t)n * (2 * HH);
    uint4 hv = {hi_p[0], hi_p[1], hi_p[2], hi_p[3]};
    uint4 lv = {lo_p[0], lo_p[1], lo_p[2], lo_p[3]};
    ((uint4*)(arow))[lane] = hv;
    ((uint4*)(arow + HH))[lane] = lv;
}

// ---------------- node predictor: warp per node, Wn in smem ----------------
__global__ void __launch_bounds__(256) k_nodepred(const float* __restrict__ h,
                                                  const float* __restrict__ Wn,
                                                  const float* __restrict__ bn,
                                                  float* __restrict__ out) {
    __shared__ float sW[OUTN * HH];
    int tid = threadIdx.x;
    for (int i = tid; i < OUTN * HH; i += 256) sW[i] = Wn[i];
    __syncthreads();
    int n = (blockIdx.x * 256 + tid) >> 5;
    int lane = tid & 31;
    if (n >= NN) return;
    const float4* hr = (const float4*)(h + (size_t)n * HH);
    float4 v0 = hr[lane * 2], v1 = hr[lane * 2 + 1];
    float p[OUTN];
#pragma unroll
    for (int o = 0; o < OUTN; o++) {
        const float4* wr = (const float4*)(sW + o * HH);
        float4 w0 = wr[lane * 2], w1 = wr[lane * 2 + 1];
        p[o] = v0.x * w0.x + v0.y * w0.y + v0.z * w0.z + v0.w * w0.w
             + v1.x * w1.x + v1.y * w1.y + v1.z * w1.z + v1.w * w1.w;
    }
#pragma unroll
    for (int off = 16; off > 0; off >>= 1)
#pragma unroll
        for (int o = 0; o < OUTN; o++)
            p[o] += __shfl_xor_sync(0xffffffffu, p[o], off);
    if (lane < OUTN) out[(size_t)n * OUTN + lane] = p[lane] + __ldg(&bn[lane]);
}

// ---------------- edge bilinear: warp per src node (src-CSR), fp16 t in registers ----------------
__global__ void k_bil(const float* __restrict__ h2, const float* __restrict__ bb,
                      float* __restrict__ out_edge) {
    int n = (blockIdx.x * blockDim.x + threadIdx.x) >> 5;
    int lane = threadIdx.x & 31;
    if (n >= NN) return;
    int start = g_offs[n], end = g_offs[n + 1];
    if (start == end) return;

    // t row: 1024 halves = 128 uint4; per o (256 halves = 32 uint4), lane takes 1 uint4 (8 halves)
    const uint4* tp = (const uint4*)(g_t + (size_t)n * (OUTE * HH));
    float tf[OUTE][8];
#pragma unroll
    for (int o = 0; o < OUTE; o++) {
        uint4 tv = tp[o * 32 + lane];
        const __half2* hp = (const __half2*)&tv;
        float2 f0 = __half22float2(hp[0]);
        float2 f1 = __half22float2(hp[1]);
        float2 f2 = __half22float2(hp[2]);
        float2 f3 = __half22float2(hp[3]);
        tf[o][0] = f0.x; tf[o][1] = f0.y; tf[o][2] = f1.x; tf[o][3] = f1.y;
        tf[o][4] = f2.x; tf[o][5] = f2.y; tf[o][6] = f3.x; tf[o][7] = f3.y;
    }
    float myb = (lane < OUTE) ? __ldg(&bb[lane]) : 0.f;

    for (int j = start; j < end; j++) {
        int d = g_dsts[j];
        int orig = g_oids[j];
        const float4* hr = (const float4*)(h2 + (size_t)d * HH);
        float4 v0 = hr[lane * 2], v1 = hr[lane * 2 + 1];
        float p[OUTE];
#pragma unroll
        for (int o = 0; o < OUTE; o++)
            p[o] = tf[o][0] * v0.x + tf[o][1] * v0.y + tf[o][2] * v0.z + tf[o][3] * v0.w
                 + tf[o][4] * v1.x + tf[o][5] * v1.y + tf[o][6] * v1.z + tf[o][7] * v1.w;
#pragma unroll
        for (int off = 16; off > 0; off >>= 1)
#pragma unroll
            for (int o = 0; o < OUTE; o++)
                p[o] += __shfl_xor_sync(0xffffffffu, p[o], off);
        if (lane < OUTE) {
            float r = (lane == 0) ? p[0] : (lane == 1) ? p[1] : (lane == 2) ? p[2] : p[3];
            out_edge[(size_t)orig * OUTE + lane] = r + myb;
        }
    }
}

// ---------------- host ----------------
extern "C" void kernel_launch(void* const* d_in, const int* in_sizes, int n_in,
                              void* d_out, int out_size) {
    const float* x   = (const float*)d_in[0];
    const int*   ei  = (const int*)d_in[1];
    const float* W1  = (const float*)d_in[2];
    const float* as1 = (const float*)d_in[3];
    const float* ad1 = (const float*)d_in[4];
    const float* b1  = (const float*)d_in[5];
    const float* W2  = (const float*)d_in[6];
    const float* as2 = (const float*)d_in[7];
    const float* ad2 = (const float*)d_in[8];
    const float* b2  = (const float*)d_in[9];
    const float* Wn  = (const float*)d_in[10];
    const float* bn  = (const float*)d_in[11];
    const float* Wb  = (const float*)d_in[12];
    const float* bb  = (const float*)d_in[13];

    float* out_node = (float*)d_out;
    float* out_edge = out_node + (size_t)NN * OUTN;
    float* out_h    = out_edge + (size_t)EE * OUTE;

    float *p_xp, *p_h1;
    __half *p_t, *p_a2, *p_b2a, *p_b2b, *p_b2c;
    int *p_cntd, *p_cnts;
    cudaGetSymbolAddress((void**)&p_xp, g_xp);
    cudaGetSymbolAddress((void**)&p_h1, g_h1);
    cudaGetSymbolAddress((void**)&p_t, g_t);
    cudaGetSymbolAddress((void**)&p_a2, g_a2);
    cudaGetSymbolAddress((void**)&p_b2a, g_b2a);
    cudaGetSymbolAddress((void**)&p_b2b, g_b2b);
    cudaGetSymbolAddress((void**)&p_b2c, g_b2c);
    cudaGetSymbolAddress((void**)&p_cntd, g_cntd);
    cudaGetSymbolAddress((void**)&p_cnts, g_cnts);

    // one-time host resources
    static cudaStream_t s2 = nullptr;
    static cudaEvent_t e0 = nullptr, e2 = nullptr, e3 = nullptr, e4 = nullptr;
    if (!s2) {
        cudaStreamCreateWithFlags(&s2, cudaStreamNonBlocking);
        cudaEventCreateWithFlags(&e0, cudaEventDisableTiming);
        cudaEventCreateWithFlags(&e2, cudaEventDisableTiming);
        cudaEventCreateWithFlags(&e3, cudaEventDisableTiming);
        cudaEventCreateWithFlags(&e4, cudaEventDisableTiming);
    }

    dim3 blk(256);
    int g_nodeW = (NN * 32 + 255) / 256;     // warp-per-node grids
    int g_esl   = (ESL + 255) / 256;

    // ---- fork: s2 memsets first, then main-stream L1 path, interleaved so
    //      ncu's -s 5 -c 1 capture (6th launch incl. memsets) lands on the L1 GEMM.
    cudaEventRecord(e0, 0);
    cudaStreamWaitEvent(s2, e0, 0);
    cudaMemsetAsync(p_cntd, 0, NN * sizeof(int), s2);   // launch 1
    cudaMemsetAsync(p_cnts, 0, NN * sizeof(int), s2);   // launch 2

    k_split2<<<(NN * INCH + 255) / 256, blk>>>(x, p_a2, NN, INCH);      // 3
    k_wsplit2<<<(HH * INCH + 255) / 256, blk>>>(W1, p_b2a, HH, INCH);   // 4
    k_hist<<<g_esl, blk, 0, s2>>>(ei);                                  // 5
    {
        dim3 grid((HH + 127) / 128, (NN + 127) / 128);
        gemm_f16_nt<<<grid, blk>>>(p_a2, p_b2a, p_xp, nullptr, NN, HH, 2 * INCH); // 6 <- profiled
    }
    k_scan2<<<2, 1024, 0, s2>>>();
    k_scatter<<<g_esl, blk, 0, s2>>>(ei);
    k_wsplit2<<<(HH * HH + 255) / 256, blk, 0, s2>>>(W2, p_b2b, HH, HH);
    k_wbt_split2<<<(OUTE * HH * HH + 255) / 256, blk, 0, s2>>>(Wb);
    cudaEventRecord(e2, s2);

    k_al<<<g_nodeW, blk>>>(as1, ad1);
    cudaStreamWaitEvent(0, e2, 0);             // join: need CSR before k_gat
    k_gat<<<g_nodeW, blk>>>(b1, p_h1, p_a2);   // h1 fp32 + split a2

    // ---- layer 2 ----
    {
        dim3 grid((HH + 127) / 128, (NN + 127) / 128);
        gemm_f16_nt<<<grid, blk>>>(p_a2, p_b2b, p_xp, nullptr, NN, HH, 2 * HH);
    }
    k_al<<<g_nodeW, blk>>>(as2, ad2);
    k_gat<<<g_nodeW, blk>>>(b2, out_h, p_a2);  // out_h fp32 + split a2

    // ---- fork: node predictor on s2, concurrent with t-GEMM ----
    cudaEventRecord(e3, 0);
    cudaStreamWaitEvent(s2, e3, 0);
    k_nodepred<<<(NN * 32 + 255) / 256, blk, 0, s2>>>(out_h, Wn, bn, out_node);
    cudaEventRecord(e4, s2);

    // ---- t = h @ WbT (fp16 output), then per-edge bilinear dot ----
    {
        dim3 grid((OUTE * HH) / 128, (NN + 127) / 128);
        gemm_f16_nt<<<grid, blk>>>(p_a2, p_b2c, nullptr, p_t, NN, OUTE * HH, 2 * HH);
    }
    k_bil<<<g_nodeW, blk>>>(out_h, bb, out_edge);
    cudaStreamWaitEvent(0, e4, 0);             // join before return
}